// round 6
// baseline (speedup 1.0000x reference)
#include <cuda_runtime.h>
#include <cuda_fp16.h>

#define HH 128
#define WW 128
#define BB 64
#define OO 32
#define NPIX (HH * WW)
#define TPB 256

// 2 MB transposed fp16 copy of X: XT[src_pixel][b], b contiguous
__device__ __half g_XT[NPIX * BB];

__global__ __launch_bounds__(256) void transpose_kernel(const float* __restrict__ X)
{
    __shared__ float t[32][33];
    const int s0 = blockIdx.x * 32;
    const int b0 = blockIdx.y * 32;
    const int tx = threadIdx.x & 31;
    const int ty = threadIdx.x >> 5;   // 0..7
    #pragma unroll
    for (int r = ty; r < 32; r += 8)
        t[tx][r] = X[(size_t)(b0 + r) * NPIX + s0 + tx];
    __syncthreads();
    #pragma unroll
    for (int r = ty; r < 32; r += 8)
        g_XT[(size_t)(s0 + r) * BB + b0 + tx] = __float2half(t[r][tx]);
}

__global__ __launch_bounds__(TPB) void dalayer_kernel(
    const float* __restrict__ eps,
    const float* __restrict__ tmin,
    const float* __restrict__ tmax,
    float* __restrict__ out)
{
    // XOR-swizzled split planes: even/odd b.  col = lane ^ (x&31)
    __shared__ float se[WW][32];
    __shared__ float so[WW][32];

    const int tid  = threadIdx.x;
    const int lane = tid & 31;
    const int warp = tid >> 5;           // 0..7
    const int y = blockIdx.x;
    const int o = blockIdx.y;

    // ---- affine params for this o (uniform per CTA) ----
    float th[7];
    #pragma unroll
    for (int i = 0; i < 7; i++) {
        const float mn = tmin[i];
        th[i] = fmaf(tmax[i] - mn, eps[o * 7 + i], mn);
    }
    float s, c;
    sincosf(th[0], &s, &c);
    const float sx = th[1], sy = th[2], pX = th[3], pY = th[4], tx = th[5], ty = th[6];
    const float a00 = c * sx - s * pY;
    const float a01 = c * pX - s * sy;
    const float a10 = s * sx + c * pY;
    const float a11 = s * pX + c * sy;
    // pixel coords: px = a00*x + a01*y + offx   [(2/127)*63.5 == 1 exactly]
    const float offx = 63.5f * (tx + 1.0f - a00 - a01);
    const float offy = 63.5f * (ty + 1.0f - a10 - a11);

    const float rowx = fmaf(a01, (float)y, offx);
    const float rowy = fmaf(a11, (float)y, offy);

    // ---- compute: warp w handles x = 16w..16w+15; lane = b-pair {2l, 2l+1} ----
    #pragma unroll 4
    for (int i = 0; i < 16; i++) {
        const int x = warp * 16 + i;

        const float cx = fminf(fmaxf(fmaf(a00, (float)x, rowx), 0.0f), 126.99999f);
        const float cy = fminf(fmaxf(fmaf(a10, (float)x, rowy), 0.0f), 126.99999f);
        const int x0 = (int)cx;
        const int y0 = (int)cy;
        const float wx = cx - (float)x0;
        const float wy = cy - (float)y0;

        // fp16 taps: each line is 128B -> 1 wavefront per tap, fully coalesced
        const __half2* p = reinterpret_cast<const __half2*>(
                               g_XT + (size_t)(y0 * WW + x0) * BB) + lane;
        const float2 Ia = __half22float2(p[0]);
        const float2 Ic = __half22float2(p[32]);            // (x0+1, y0)
        const float2 Ib = __half22float2(p[WW * 32]);       // (x0,   y0+1)
        const float2 Id = __half22float2(p[WW * 32 + 32]);  // (x0+1, y0+1)

        float rx, ry;
        {
            const float t0 = fmaf(wx, Ic.x - Ia.x, Ia.x);
            const float t1 = fmaf(wx, Id.x - Ib.x, Ib.x);
            rx = fmaf(wy, t1 - t0, t0);
        }
        {
            const float t0 = fmaf(wx, Ic.y - Ia.y, Ia.y);
            const float t1 = fmaf(wx, Id.y - Ib.y, Ib.y);
            ry = fmaf(wy, t1 - t0, t0);
        }
        const int col = lane ^ (x & 31);
        se[x][col] = rx;     // b = 2*lane   : conflict-free (permutation)
        so[x][col] = ry;     // b = 2*lane+1 : conflict-free
    }

    __syncthreads();

    // ---- writeout: warp w handles b = 8w..8w+7; conflict-free LDS, coalesced STG ----
    #pragma unroll
    for (int b8 = 0; b8 < 8; b8++) {
        const int b = warp * 8 + b8;
        const int hb = b >> 1;
        const float (*plane)[32] = (b & 1) ? so : se;
        float* __restrict__ dst = out + (size_t)(o * BB + b) * NPIX + y * WW;
        #pragma unroll
        for (int j = 0; j < 4; j++) {
            const int x = j * 32 + lane;
            dst[x] = plane[x][hb ^ lane];      // bank = (hb^lane) -> permutation
        }
    }
}

extern "C" void kernel_launch(void* const* d_in, const int* in_sizes, int n_in,
                              void* d_out, int out_size)
{
    const float* X    = (const float*)d_in[0];
    const float* eps  = (const float*)d_in[1];
    const float* tmin = (const float*)d_in[2];
    const float* tmax = (const float*)d_in[3];
    float* out = (float*)d_out;

    dim3 tgrid(NPIX / 32, BB / 32);            // 512 x 2
    transpose_kernel<<<tgrid, 256>>>(X);

    dim3 grid(HH, OO);                         // 128 x 32 CTAs
    dalayer_kernel<<<grid, TPB>>>(eps, tmin, tmax, out);
}

// round 7
// speedup vs baseline: 1.1822x; 1.1822x over previous
#include <cuda_runtime.h>
#include <cuda_fp16.h>

#define HH 128
#define WW 128
#define BB 64
#define OO 32
#define NPIX (HH * WW)
#define TPB 256

// 2 MB transposed fp16 copy of X: XT[src_pixel][b], b contiguous
__device__ __half g_XT[NPIX * BB];
// precomputed affine params per o: {a00, a10, a01, a11} and {offx, offy}
__device__ float4 g_aff[OO];
__device__ float2 g_off[OO];

__global__ __launch_bounds__(32) void setup_kernel(
    const float* __restrict__ eps,
    const float* __restrict__ tmin,
    const float* __restrict__ tmax)
{
    const int o = threadIdx.x;
    float th[7];
    #pragma unroll
    for (int i = 0; i < 7; i++) {
        const float mn = tmin[i];
        th[i] = fmaf(tmax[i] - mn, eps[o * 7 + i], mn);
    }
    float s, c;
    sincosf(th[0], &s, &c);
    const float sx = th[1], sy = th[2], pX = th[3], pY = th[4], tx = th[5], ty = th[6];
    const float a00 = c * sx - s * pY;
    const float a01 = c * pX - s * sy;
    const float a10 = s * sx + c * pY;
    const float a11 = s * pX + c * sy;
    // pixel coords: px = a00*x + a01*y + offx   [(2/127)*63.5 == 1 exactly]
    g_aff[o] = make_float4(a00, a10, a01, a11);
    g_off[o] = make_float2(63.5f * (tx + 1.0f - a00 - a01),
                           63.5f * (ty + 1.0f - a10 - a11));
}

__global__ __launch_bounds__(256) void transpose_kernel(const float* __restrict__ X)
{
    __shared__ float t[BB][33];
    const int s0   = blockIdx.x * 32;
    const int lane = threadIdx.x & 31;
    const int warp = threadIdx.x >> 5;      // 0..7
    #pragma unroll
    for (int r = 0; r < 8; r++) {
        const int b = warp * 8 + r;
        t[b][lane] = X[(size_t)b * NPIX + s0 + lane];
    }
    __syncthreads();
    __half2* dst = reinterpret_cast<__half2*>(g_XT);
    #pragma unroll
    for (int r = 0; r < 4; r++) {
        const int sl = r * 8 + warp;        // 0..31
        dst[(size_t)(s0 + sl) * 32 + lane] =
            __floats2half2_rn(t[2 * lane][sl], t[2 * lane + 1][sl]);
    }
}

__global__ __launch_bounds__(TPB) void dalayer_kernel(float* __restrict__ out)
{
    // one swizzled half2 plane: element [x][col] holds b-pair (col ^ (x&31))
    __shared__ __half2 plane[WW][32];       // 16 KB

    const int tid  = threadIdx.x;
    const int lane = tid & 31;
    const int warp = tid >> 5;              // 0..7
    const int y = blockIdx.x;
    const int o = blockIdx.y;

    const float4 A  = g_aff[o];             // broadcast L2 loads
    const float2 Of = g_off[o];
    const float a00 = A.x, a10 = A.y, a01 = A.z, a11 = A.w;

    const float rowx = fmaf(a01, (float)y, Of.x);
    const float rowy = fmaf(a11, (float)y, Of.y);

    // ---- compute: warp w handles x = 16w..16w+15; lane = b-pair {2l, 2l+1} ----
    #pragma unroll 4
    for (int i = 0; i < 16; i++) {
        const int x = warp * 16 + i;

        const float cx = fminf(fmaxf(fmaf(a00, (float)x, rowx), 0.0f), 126.99999f);
        const float cy = fminf(fmaxf(fmaf(a10, (float)x, rowy), 0.0f), 126.99999f);
        const int x0 = (int)cx;
        const int y0 = (int)cy;
        const __half2 wx2 = __float2half2_rn(cx - (float)x0);
        const __half2 wy2 = __float2half2_rn(cy - (float)y0);

        // fp16 taps: each line is 128B -> 1 coalesced wavefront per tap
        const __half2* p = reinterpret_cast<const __half2*>(g_XT)
                           + (size_t)(y0 * WW + x0) * 32 + lane;
        const __half2 Ia = p[0];
        const __half2 Ic = p[32];            // (x0+1, y0)
        const __half2 Ib = p[WW * 32];       // (x0,   y0+1)
        const __half2 Id = p[WW * 32 + 32];  // (x0+1, y0+1)

        const __half2 t0 = __hfma2(wx2, __hsub2(Ic, Ia), Ia);
        const __half2 t1 = __hfma2(wx2, __hsub2(Id, Ib), Ib);
        const __half2 r  = __hfma2(wy2, __hsub2(t1, t0), t0);

        plane[x][lane ^ (x & 31)] = r;       // bank = lane^(x&31): conflict-free
    }

    __syncthreads();

    // ---- writeout: warp w handles b-pairs p = 4w..4w+3; lane = x mod 32 ----
    #pragma unroll
    for (int pp = 0; pp < 4; pp++) {
        const int p = warp * 4 + pp;         // b = 2p, 2p+1
        float* __restrict__ d0 = out + (size_t)(o * BB + 2 * p) * NPIX + y * WW;
        float* __restrict__ d1 = d0 + NPIX;
        #pragma unroll
        for (int j = 0; j < 4; j++) {
            const int x = j * 32 + lane;
            const float2 v = __half22float2(plane[x][p ^ lane]); // bank perm: conflict-free
            d0[x] = v.x;
            d1[x] = v.y;
        }
    }
}

extern "C" void kernel_launch(void* const* d_in, const int* in_sizes, int n_in,
                              void* d_out, int out_size)
{
    const float* X    = (const float*)d_in[0];
    const float* eps  = (const float*)d_in[1];
    const float* tmin = (const float*)d_in[2];
    const float* tmax = (const float*)d_in[3];
    float* out = (float*)d_out;

    setup_kernel<<<1, 32>>>(eps, tmin, tmax);
    transpose_kernel<<<NPIX / 32, 256>>>(X);

    dim3 grid(HH, OO);                       // 128 x 32 CTAs
    dalayer_kernel<<<grid, TPB>>>(out);
}